// round 15
// baseline (speedup 1.0000x reference)
#include <cuda_runtime.h>
#include <cuda_fp16.h>
#include <math.h>

#define BB 512
#define HH 64
#define LL 528
#define DD 32
#define NIV 64
#define WW 128
#define NSTEPS 256
#define LSTR (65*529)       // logsig batch stride
#define GRIDN 132
#define GROUPC 33
#define THREADS 512

// ---------------- scratch (device globals; no allocation allowed) ----------
__device__ float g_y[BB*HH];
__device__ float g_k[6][BB*HH];
__device__ float g_part[132*128*64];   // per-CTA k partials [cta][row_local][h]
__device__ __half g_h3h[BB*WW];
// W3 in fragment-linear layout: [lc(33)][h(64)] blocks of 4KB;
// within a block: lane*128B + c*16B + j*4B  (j: b0L,b1L,b0H,b1H)
__device__ __half g_w3f[33*64*2048];
__device__ __half g_w0h[WW*HH];
__device__ __half g_w1h[WW*WW];
__device__ __half g_w2h[WW*WW];
__device__ float g_scal[2];            // t0, dt
__device__ unsigned g_barg[4];         // per-group barrier counters (wrap to 0)

// ---------------- RK coefficients ----------------
__constant__ float cA[6][5] = {
  {0.f,0.f,0.f,0.f,0.f},
  {0.161f,0.f,0.f,0.f,0.f},
  {-0.008480655492356989f,0.335480655492357f,0.f,0.f,0.f},
  {2.8971530571054935f,-6.359448489975075f,4.3622954328695815f,0.f,0.f},
  {5.325864828439257f,-11.748883564062828f,7.4955393428898365f,-0.09249506636175525f,0.f},
  {5.86145544294642f,-12.92096931784711f,8.159367898576159f,-0.071584973281401f,-0.028269050394068383f}
};
__constant__ float cBv[6] = {0.09646076681806523f,0.01f,0.4798896504144996f,
                             1.379008574103742f,-3.290069515436081f,2.324710524099774f};
__constant__ float cCv[6] = {0.f,0.161f,0.327f,0.9f,0.9800255409045097f,1.0f};

// ---------------- smem layout (byte offsets) -------------------------------
#define OFF_W0   0        // half [128][72]    18432 B (phase A weights)
#define OFF_W1   18432    // half [128][136]   34816 B
#define OFF_W2   53248    // half [128][136]   34816 B
#define OFF_AB   88064    // float[384]         1536 B
#define OFF_A0   89600    // half [16][136]     4352 B
#define OFF_A1   93952    // half [16][136]     4352 B
#define OFF_SA   98304    // half [128][136]   34816 B (h3 tile)
#define OFF_SG   133120   // half2 [8][136]     4352 B (sig pairs)
#define OFF_B3   137472   // half2 [64][8]      2048 B (bias pairs)
#define OFF_SK   139520   // float [128][65]   33280 B (k partial accum)
#define SMEM_TOT 172800

// ---------------- helpers ----------------
__device__ __forceinline__ void mma_f16(float c[4],
        unsigned a0, unsigned a1, unsigned a2, unsigned a3,
        unsigned b0, unsigned b1){
    asm volatile(
      "mma.sync.aligned.m16n8k16.row.col.f32.f16.f16.f32 "
      "{%0,%1,%2,%3},{%4,%5,%6,%7},{%8,%9},{%0,%1,%2,%3};"
      : "+f"(c[0]), "+f"(c[1]), "+f"(c[2]), "+f"(c[3])
      : "r"(a0), "r"(a1), "r"(a2), "r"(a3), "r"(b0), "r"(b1));
}
__device__ __forceinline__ void ldsm_x4(unsigned &r0, unsigned &r1,
        unsigned &r2, unsigned &r3, unsigned addr){
    asm volatile("ldmatrix.sync.aligned.m8n8.x4.shared.b16 {%0,%1,%2,%3}, [%4];"
        : "=r"(r0), "=r"(r1), "=r"(r2), "=r"(r3) : "r"(addr));
}
__device__ __forceinline__ float tanha(float x){
    float r; asm("tanh.approx.f32 %0, %1;" : "=f"(r) : "f"(x)); return r;
}
__device__ __forceinline__ __half2 tanh2(__half2 x){
    unsigned xi = *reinterpret_cast<unsigned*>(&x);
    unsigned r;
    asm("tanh.approx.f16x2 %0, %1;" : "=r"(r) : "r"(xi));
    return *reinterpret_cast<__half2*>(&r);
}
__device__ __forceinline__ float fast_silu(float z){
    return z * (0.5f * (1.0f + tanha(0.5f*z)));
}
__device__ __forceinline__ unsigned sm32(const void* p){
    return (unsigned)__cvta_generic_to_shared(p);
}
#define CPA16(d, s) asm volatile("cp.async.cg.shared.global [%0], [%1], 16;\n" :: "r"(d), "l"(s))
#define CPCOMMIT()  asm volatile("cp.async.commit_group;\n")
#define CPWAIT(n)   asm volatile("cp.async.wait_group %0;\n" :: "n"(n))

// Per-group monotonic barrier; counter wraps to exactly 0 at run end
// (2*NSTEPS*6 barriers x 33 arrivals = 101376 increments) -> replay-invariant.
__device__ __forceinline__ void group_barrier(int grp, unsigned target){
    __syncthreads();
    if (threadIdx.x == 0){
        const unsigned wrapm1 = 101376u - 1u;
        __threadfence();
        atomicInc(&g_barg[grp], wrapm1);
        unsigned lo = target - GROUPC;
        unsigned v;
        do {
            asm volatile("ld.acquire.gpu.u32 %0, [%1];" : "=r"(v) : "l"(&g_barg[grp]) : "memory");
        } while (v < target && v >= lo);
    }
    __syncthreads();
}

// ================= dummy kernels (shift ncu -s window onto k_main) =========
__global__ void k_nop(){}

// ================= init: y0, fp16 weights (incl. W3 fragment layout) =======
__global__ void k_init(const float* __restrict__ ts, const float* __restrict__ x0,
                       const float* __restrict__ l1w, const float* __restrict__ l1b,
                       const float* __restrict__ w0, const float* __restrict__ w1,
                       const float* __restrict__ w2, const float* __restrict__ w3){
    long tid = (long)blockIdx.x*blockDim.x + threadIdx.x;
    long stride = (long)gridDim.x*blockDim.x;
    if (tid == 0){
        g_scal[0] = ts[0];
        g_scal[1] = (ts[128] - ts[0]) / 256.0f;
    }
    if (tid < BB*HH){
        int b = (int)(tid/HH), h = (int)(tid%HH);
        float acc = l1b[h];
        #pragma unroll
        for (int d = 0; d < DD; d++) acc += x0[b*DD+d]*l1w[h*DD+d];
        g_y[tid] = acc;
    }
    for (long i = tid; i < WW*HH; i += stride) g_w0h[i] = __float2half_rn(w0[i]);
    for (long i = tid; i < WW*WW; i += stride) g_w1h[i] = __float2half_rn(w1[i]);
    for (long i = tid; i < WW*WW; i += stride) g_w2h[i] = __float2half_rn(w2[i]);
    // W3 fragment-linear layout: half2 unit index bits =
    //   lc*65536 + h*1024 + lane*32 + c*4 + j
    // j0: (n=lane>>2,   k=c*16+(lane&3)*2)   j1: same n, k+8
    // j2: (n=8+lane>>2, k=c*16+(lane&3)*2)   j3: same n, k+8
    const long NU = 33L*65536;  // 2,162,688 half2 units (only lc<33 valid)
    for (long u = tid; u < NU; u += stride){
        int j = (int)(u & 3);
        int c = (int)((u >> 2) & 7);
        int lane = (int)((u >> 5) & 31);
        int h = (int)((u >> 10) & 63);
        int lc = (int)(u >> 16);
        int n = (lane >> 2) + ((j >> 1) ? 8 : 0);
        int l = lc*16 + n;
        int k = c*16 + (lane & 3)*2 + ((j & 1) ? 8 : 0);
        const float* src = w3 + ((size_t)h*LL + l)*WW + k;
        reinterpret_cast<__half2*>(g_w3f)[u] = __floats2half2_rn(src[0], src[1]);
    }
}

// ---------------- one fp16 MLP layer (phase A, N=8 per warp) ---------------
__device__ __forceinline__ void mlpA(const __half* cur, const __half* wsm,
        int wstr32, int nch, const float* __restrict__ bias,
        __half* nxt, __half* h3out, int rbase, int g, int tg, int nb, int nrows){
    const unsigned* cu = (const unsigned*)cur;
    const unsigned* wu = (const unsigned*)wsm;
    float acc[4] = {0.f,0.f,0.f,0.f};
    for (int ch = 0; ch < nch; ch++){
        unsigned a0 = cu[ g   *68 + ch*8 + tg  ];
        unsigned a1 = cu[(g+8)*68 + ch*8 + tg  ];
        unsigned a2 = cu[ g   *68 + ch*8 + tg+4];
        unsigned a3 = cu[(g+8)*68 + ch*8 + tg+4];
        unsigned b0 = wu[(nb+g)*wstr32 + ch*8 + tg  ];
        unsigned b1 = wu[(nb+g)*wstr32 + ch*8 + tg+4];
        mma_f16(acc, a0,a1,a2,a3, b0,b1);
    }
    int colb = nb + 2*tg;
    float z0 = acc[0]+bias[colb], z1 = acc[1]+bias[colb+1];
    __half2 v0 = __floats2half2_rn(fast_silu(z0), fast_silu(z1));
    if (h3out){
        if (g < nrows)
            *reinterpret_cast<__half2*>(&h3out[(rbase+g)*WW + colb]) = v0;
    } else {
        float z2 = acc[2]+bias[colb], z3 = acc[3]+bias[colb+1];
        __half2 v1 = __floats2half2_rn(fast_silu(z2), fast_silu(z3));
        *reinterpret_cast<__half2*>(&nxt[ g   *136 + colb]) = v0;
        *reinterpret_cast<__half2*>(&nxt[(g+8)*136 + colb]) = v1;
    }
}

// ================= persistent main kernel (512 threads, 132 CTAs) ==========
__global__ void __launch_bounds__(THREADS, 1) k_main(
        const float* __restrict__ logsig, const float* __restrict__ intervals,
        const float* __restrict__ b0, const float* __restrict__ b1,
        const float* __restrict__ b2, const float* __restrict__ b3){
    extern __shared__ char smc[];
    __half*  w0s   = (__half*) (smc + OFF_W0);
    __half*  w1s   = (__half*) (smc + OFF_W1);
    __half*  w2s   = (__half*) (smc + OFF_W2);
    float*   abias = (float*)  (smc + OFF_AB);
    __half*  act0  = (__half*) (smc + OFF_A0);
    __half*  act1  = (__half*) (smc + OFF_A1);
    __half*  sA    = (__half*) (smc + OFF_SA);
    __half2* sSig2 = (__half2*)(smc + OFF_SG);
    __half2* sBb3h = (__half2*)(smc + OFF_B3);
    float*   sK    = (float*)  (smc + OFF_SK);

    const int tid = threadIdx.x;
    const int cta = blockIdx.x;
    const int grp = cta / GROUPC;
    const int member = cta - grp*GROUPC;      // 0..32 (= l-chunk)
    const int wid = tid >> 5, lane = tid & 31;
    const int g = lane >> 2, tg = lane & 3;
    const float t0 = g_scal[0], dt = g_scal[1];
    unsigned bt = 0;

    const unsigned sAa = sm32(smc + OFF_SA);

    // ---- preamble: phase-A weights resident in smem for the whole run ----
    {
        unsigned w0a = sm32(w0s), w1a = sm32(w1s), w2a = sm32(w2s);
        #pragma unroll
        for (int j = 0; j < 2; j++){
            int id = tid + j*THREADS; int r = id >> 3, q = id & 7;
            CPA16(w0a + (unsigned)(r*144 + q*16), (const void*)((const char*)g_w0h + r*128 + q*16));
        }
        #pragma unroll
        for (int j = 0; j < 4; j++){
            int id = tid + j*THREADS; int r = id >> 4, q = id & 15;
            CPA16(w1a + (unsigned)(r*272 + q*16), (const void*)((const char*)g_w1h + r*256 + q*16));
        }
        #pragma unroll
        for (int j = 0; j < 4; j++){
            int id = tid + j*THREADS; int r = id >> 4, q = id & 15;
            CPA16(w2a + (unsigned)(r*272 + q*16), (const void*)((const char*)g_w2h + r*256 + q*16));
        }
        CPCOMMIT();
        if (tid < 384)
            abias[tid] = (tid < 128) ? b0[tid] : (tid < 256) ? b1[tid-128] : b2[tid-256];
        CPWAIT(0);
    }
    __syncthreads();

    // phase-B per-warp constants (16 warps = 8 M-tiles x 2 h-slots)
    const int mt = wid & 7, nh = wid >> 3;
    const int mrow = mt * 16;
    const int arow = mrow + (lane & 7) + (lane & 8);
    const int kofA = ((lane >> 4) & 1) * 8;
    const int rbase = grp * 128;
    const int l0 = member * 16;
    const char* wfbase = (const char*)g_w3f + ((size_t)member << 18) + lane*128;

    for (int step = 0; step < NSTEPS; step++){
        for (int s = 0; s < 6; s++){
            // ------- Phase A: members 0..31, 4 rows each (btile-local) -----
            if (member < 32){
                int rbaseA = rbase + member*4;
                if (tid < 256){
                    int r = tid >> 6, h = tid & 63;
                    int gi = (rbaseA + r)*HH + h;
                    int prev = (s + 5) % 6;
                    float kp = 0.f;
                    if (step > 0 || s > 0){
                        size_t base = (size_t)grp*GROUPC*8192
                                    + (size_t)((member*4 + r)*64 + h);
                        #pragma unroll
                        for (int j = 0; j < GROUPC; j++)
                            kp += g_part[base + (size_t)j*8192];
                        g_k[prev][gi] = kp;
                    }
                    float y = g_y[gi];
                    if (s == 0){
                        if (step > 0){
                            float a = cBv[5]*kp;
                            #pragma unroll
                            for (int j = 0; j < 5; j++) a += cBv[j]*g_k[j][gi];
                            y += dt*a;
                            g_y[gi] = y;
                        }
                    } else {
                        float a = cA[s][s-1]*kp;
                        for (int j = 0; j < s-1; j++) a += cA[s][j]*g_k[j][gi];
                        y += dt*a;
                    }
                    act0[r*136 + h] = __float2half_rn(y);
                }
                if (tid < 384){   // zero pad rows 4..15, cols 0..63
                    int rr = 4 + (tid >> 5);
                    ((unsigned*)act0)[rr*68 + (tid & 31)] = 0u;
                }
                __syncthreads();
                int nb = wid * 8;
                mlpA(act0, w0s, 36, 4, abias,       act1, nullptr, rbaseA, g, tg, nb, 4);
                __syncthreads();
                mlpA(act1, w1s, 68, 8, abias + 128, act0, nullptr, rbaseA, g, tg, nb, 4);
                __syncthreads();
                mlpA(act0, w2s, 68, 8, abias + 256, nullptr, g_h3h, rbaseA, g, tg, nb, 4);
            }
            bt += GROUPC; group_barrier(grp, bt);

            // ------- Phase B: fp16 GEMM, B fragments via LDG.128 -----------
            {
                float t = t0 + (float)step*dt + cCv[s]*dt;
                int idx = 0;
                #pragma unroll
                for (int j = 0; j < NIV; j++) idx += (intervals[j] < t) ? 1 : 0;

                // stage h3 tile (fp16, 32 KB)
                #pragma unroll
                for (int j = 0; j < 4; j++){
                    int id = tid + j*THREADS; int r = id >> 4, q = id & 15;
                    float4 v = *reinterpret_cast<const float4*>(
                        (const char*)g_h3h + (size_t)(rbase + r)*256 + q*16);
                    *reinterpret_cast<float4*>((char*)sA + r*272 + q*16) = v;
                }
                // sig pairs -> half2 [lpair][row]
                #pragma unroll
                for (int j = 0; j < 2; j++){
                    int e = tid + j*THREADS;
                    int r = e >> 3, p = e & 7;
                    const float* src = logsig + (size_t)(rbase + r)*LSTR
                                     + (size_t)idx*529 + 1 + l0 + 2*p;
                    sSig2[p*136 + r] = __floats2half2_rn(src[0], src[1]);
                }
                // bias pairs -> half2 [h][lpair]
                {
                    int h = tid >> 3, p = tid & 7;
                    sBb3h[h*8 + p] = __floats2half2_rn(b3[h*LL + l0 + 2*p],
                                                       b3[h*LL + l0 + 2*p + 1]);
                }
                __syncthreads();

                // A fragments register-resident for the whole stage
                unsigned aF[8][4];
                #pragma unroll
                for (int ch = 0; ch < 8; ch++)
                    ldsm_x4(aF[ch][0], aF[ch][1], aF[ch][2], aF[ch][3],
                            sAa + (unsigned)(arow*272 + (ch*16 + kofA)*2));

                // prefetch B fragments for first h
                uint4 Bv[8];
                {
                    const uint4* wf = (const uint4*)(wfbase + ((size_t)nh << 12));
                    #pragma unroll
                    for (int c = 0; c < 8; c++) Bv[c] = wf[c];
                }

                const int rg = mrow + g, rg8 = rg + 8;
                for (int t2 = 0; t2 < 32; t2++){
                    int h = 2*t2 + nh;
                    float accL[4] = {0.f,0.f,0.f,0.f};
                    float accH[4] = {0.f,0.f,0.f,0.f};
                    #pragma unroll
                    for (int c = 0; c < 8; c++){
                        mma_f16(accL, aF[c][0],aF[c][1],aF[c][2],aF[c][3], Bv[c].x, Bv[c].y);
                        mma_f16(accH, aF[c][0],aF[c][1],aF[c][2],aF[c][3], Bv[c].z, Bv[c].w);
                    }
                    // issue next h's B loads (covered by epilogue below)
                    if (t2 < 31){
                        const uint4* wf = (const uint4*)(wfbase + ((size_t)(h+2) << 12));
                        #pragma unroll
                        for (int c = 0; c < 8; c++) Bv[c] = wf[c];
                    }
                    // epilogue: bias + tanh(f16x2) + sig, reduce 16 l's
                    __half2 biasL = sBb3h[h*8 + tg];
                    __half2 biasH = sBb3h[h*8 + 4 + tg];
                    __half2 sigLa = sSig2[tg*136 + rg],     sigLb = sSig2[tg*136 + rg8];
                    __half2 sigHa = sSig2[(4+tg)*136 + rg], sigHb = sSig2[(4+tg)*136 + rg8];
                    __half2 zL0 = __hadd2(__floats2half2_rn(accL[0],accL[1]), biasL);
                    __half2 zH0 = __hadd2(__floats2half2_rn(accH[0],accH[1]), biasH);
                    __half2 zL1 = __hadd2(__floats2half2_rn(accL[2],accL[3]), biasL);
                    __half2 zH1 = __hadd2(__floats2half2_rn(accH[2],accH[3]), biasH);
                    __half2 p0 = __hmul2(tanh2(zL0), sigLa);
                    p0 = __hfma2(tanh2(zH0), sigHa, p0);
                    __half2 p1 = __hmul2(tanh2(zL1), sigLb);
                    p1 = __hfma2(tanh2(zH1), sigHb, p1);
                    float2 f0 = __half22float2(p0); float s0 = f0.x + f0.y;
                    float2 f1 = __half22float2(p1); float s1 = f1.x + f1.y;
                    s0 += __shfl_xor_sync(0xffffffffu, s0, 1);
                    s0 += __shfl_xor_sync(0xffffffffu, s0, 2);
                    s1 += __shfl_xor_sync(0xffffffffu, s1, 1);
                    s1 += __shfl_xor_sync(0xffffffffu, s1, 2);
                    if (tg == 0){
                        sK[rg *65 + h] = s0;
                        sK[rg8*65 + h] = s1;
                    }
                }
                __syncthreads();
                // flush k partials: sK -> g_part[cta]
                #pragma unroll
                for (int j = 0; j < 16; j++){
                    int e = tid + j*THREADS;
                    int rr = e >> 6, hh = e & 63;
                    g_part[(size_t)cta*8192 + e] = sK[rr*65 + hh];
                }
            }
            bt += GROUPC; group_barrier(grp, bt);
        }
    }
}

// ================= final: reduce k5, y update + logits + softmax ===========
__global__ void k_final(const float* __restrict__ l2w, const float* __restrict__ l2b,
                        float* __restrict__ out){
    int b = blockIdx.x*blockDim.x + threadIdx.x;
    if (b >= BB) return;
    float dt = g_scal[1];
    int btile = b >> 7, rl = b & 127;
    size_t pbase = (size_t)(btile*GROUPC)*8192 + (size_t)rl*64;
    float yv[HH];
    for (int h = 0; h < HH; h++){
        int gi = b*HH + h;
        float k5 = 0.f;
        #pragma unroll
        for (int lc = 0; lc < GROUPC; lc++) k5 += g_part[pbase + (size_t)lc*8192 + h];
        float a = cBv[5]*k5;
        #pragma unroll
        for (int j = 0; j < 5; j++) a += cBv[j]*g_k[j][gi];
        yv[h] = g_y[gi] + dt*a;
    }
    float lg[10]; float mx = -1e30f;
    #pragma unroll
    for (int o = 0; o < 10; o++){
        float a = l2b[o];
        for (int h = 0; h < HH; h++) a += yv[h]*l2w[o*HH + h];
        lg[o] = a; mx = fmaxf(mx, a);
    }
    float ssum = 0.f;
    #pragma unroll
    for (int o = 0; o < 10; o++){ lg[o] = expf(lg[o] - mx); ssum += lg[o]; }
    float inv = 1.0f / ssum;
    #pragma unroll
    for (int o = 0; o < 10; o++) out[b*10 + o] = lg[o]*inv;
}

// ================= launcher: 5 graph nodes =================================
extern "C" void kernel_launch(void* const* d_in, const int* in_sizes, int n_in,
                              void* d_out, int out_size){
    const float* ts        = (const float*)d_in[0];
    const float* logsig    = (const float*)d_in[1];
    const float* x0        = (const float*)d_in[2];
    const float* intervals = (const float*)d_in[3];
    const float* w0 = (const float*)d_in[4];   const float* b0 = (const float*)d_in[5];
    const float* w1 = (const float*)d_in[6];   const float* b1 = (const float*)d_in[7];
    const float* w2 = (const float*)d_in[8];   const float* b2 = (const float*)d_in[9];
    const float* w3 = (const float*)d_in[10];  const float* b3 = (const float*)d_in[11];
    const float* l1w = (const float*)d_in[12]; const float* l1b = (const float*)d_in[13];
    const float* l2w = (const float*)d_in[14]; const float* l2b = (const float*)d_in[15];
    float* out = (float*)d_out;

    cudaFuncSetAttribute(k_main, cudaFuncAttributeMaxDynamicSharedMemorySize, SMEM_TOT);

    // two no-op launches keep the fixed ncu -s window on k_main
    k_nop<<<1, 32>>>();
    k_nop<<<1, 32>>>();
    k_init<<<4224, 256>>>(ts, x0, l1w, l1b, w0, w1, w2, w3);
    k_main<<<GRIDN, THREADS, SMEM_TOT>>>(logsig, intervals, b0, b1, b2, b3);
    k_final<<<2, 256>>>(l2w, l2b, out);
}

// round 16
// speedup vs baseline: 3.7385x; 3.7385x over previous
#include <cuda_runtime.h>
#include <cuda_fp16.h>
#include <math.h>

#define BB 512
#define HH 64
#define LL 528
#define DD 32
#define NIV 64
#define WW 128
#define NSTEPS 256
#define LSTR (65*529)       // logsig batch stride
#define GRIDN 132
#define GROUPC 33
#define THREADS 512

// ---------------- scratch (device globals; no allocation allowed) ----------
__device__ float g_y[BB*HH];
__device__ float g_k[6][BB*HH];
__device__ float g_part[132*128*64];   // per-CTA k partials [cta][row_local][h]
__device__ __half g_h3h[BB*WW];
// W3 fragment layout: [lc(33)][h(64)] blocks of 4KB;
// within a block: (c*32 + lane)*16B, 16B unit = {j0,j1,j2,j3} half2 frags
__device__ __half g_w3f[33*64*2048];
__device__ __half g_w0h[WW*HH];
__device__ __half g_w1h[WW*WW];
__device__ __half g_w2h[WW*WW];
__device__ float g_scal[2];            // t0, dt
__device__ unsigned g_barg[4];         // per-group barrier counters (wrap to 0)

// ---------------- RK coefficients ----------------
__constant__ float cA[6][5] = {
  {0.f,0.f,0.f,0.f,0.f},
  {0.161f,0.f,0.f,0.f,0.f},
  {-0.008480655492356989f,0.335480655492357f,0.f,0.f,0.f},
  {2.8971530571054935f,-6.359448489975075f,4.3622954328695815f,0.f,0.f},
  {5.325864828439257f,-11.748883564062828f,7.4955393428898365f,-0.09249506636175525f,0.f},
  {5.86145544294642f,-12.92096931784711f,8.159367898576159f,-0.071584973281401f,-0.028269050394068383f}
};
__constant__ float cBv[6] = {0.09646076681806523f,0.01f,0.4798896504144996f,
                             1.379008574103742f,-3.290069515436081f,2.324710524099774f};
__constant__ float cCv[6] = {0.f,0.161f,0.327f,0.9f,0.9800255409045097f,1.0f};

// ---------------- smem layout (byte offsets) -------------------------------
#define OFF_W0   0        // half [128][72]    18432 B (phase A weights)
#define OFF_W1   18432    // half [128][136]   34816 B
#define OFF_W2   53248    // half [128][136]   34816 B
#define OFF_AB   88064    // float[384]         1536 B
#define OFF_A0   89600    // half [16][136]     4352 B
#define OFF_A1   93952    // half [16][136]     4352 B
#define OFF_SA   98304    // half [128][136]   34816 B (h3 tile)
#define OFF_SG   133120   // half2 [8][136]     4352 B (sig pairs)
#define OFF_B3   137472   // half2 [64][8]      2048 B (bias pairs)
#define OFF_SK   139520   // float [128][65]   33280 B (k partial accum)
#define SMEM_TOT 172800

// ---------------- helpers ----------------
__device__ __forceinline__ void mma_f16(float c[4],
        unsigned a0, unsigned a1, unsigned a2, unsigned a3,
        unsigned b0, unsigned b1){
    asm volatile(
      "mma.sync.aligned.m16n8k16.row.col.f32.f16.f16.f32 "
      "{%0,%1,%2,%3},{%4,%5,%6,%7},{%8,%9},{%0,%1,%2,%3};"
      : "+f"(c[0]), "+f"(c[1]), "+f"(c[2]), "+f"(c[3])
      : "r"(a0), "r"(a1), "r"(a2), "r"(a3), "r"(b0), "r"(b1));
}
__device__ __forceinline__ void ldsm_x4(unsigned &r0, unsigned &r1,
        unsigned &r2, unsigned &r3, unsigned addr){
    asm volatile("ldmatrix.sync.aligned.m8n8.x4.shared.b16 {%0,%1,%2,%3}, [%4];"
        : "=r"(r0), "=r"(r1), "=r"(r2), "=r"(r3) : "r"(addr));
}
__device__ __forceinline__ float tanha(float x){
    float r; asm("tanh.approx.f32 %0, %1;" : "=f"(r) : "f"(x)); return r;
}
__device__ __forceinline__ __half2 tanh2(__half2 x){
    unsigned xi = *reinterpret_cast<unsigned*>(&x);
    unsigned r;
    asm("tanh.approx.f16x2 %0, %1;" : "=r"(r) : "r"(xi));
    return *reinterpret_cast<__half2*>(&r);
}
__device__ __forceinline__ float fast_silu(float z){
    return z * (0.5f * (1.0f + tanha(0.5f*z)));
}
__device__ __forceinline__ unsigned sm32(const void* p){
    return (unsigned)__cvta_generic_to_shared(p);
}
#define CPA16(d, s) asm volatile("cp.async.cg.shared.global [%0], [%1], 16;\n" :: "r"(d), "l"(s))
#define CPCOMMIT()  asm volatile("cp.async.commit_group;\n")
#define CPWAIT(n)   asm volatile("cp.async.wait_group %0;\n" :: "n"(n))

// Per-group monotonic barrier; counter wraps to exactly 0 at run end
// (2*NSTEPS*6 barriers x 33 arrivals = 101376 increments) -> replay-invariant.
__device__ __forceinline__ void group_barrier(int grp, unsigned target){
    __syncthreads();
    if (threadIdx.x == 0){
        const unsigned wrapm1 = 101376u - 1u;
        __threadfence();
        atomicInc(&g_barg[grp], wrapm1);
        unsigned lo = target - GROUPC;
        unsigned v;
        do {
            asm volatile("ld.acquire.gpu.u32 %0, [%1];" : "=r"(v) : "l"(&g_barg[grp]) : "memory");
        } while (v < target && v >= lo);
    }
    __syncthreads();
}

// ================= dummy kernels (shift ncu -s window onto k_main) =========
__global__ void k_nop(){}

// ================= init: y0, fp16 weights (incl. W3 fragment layout) =======
__global__ void k_init(const float* __restrict__ ts, const float* __restrict__ x0,
                       const float* __restrict__ l1w, const float* __restrict__ l1b,
                       const float* __restrict__ w0, const float* __restrict__ w1,
                       const float* __restrict__ w2, const float* __restrict__ w3){
    long tid = (long)blockIdx.x*blockDim.x + threadIdx.x;
    long stride = (long)gridDim.x*blockDim.x;
    if (tid == 0){
        g_scal[0] = ts[0];
        g_scal[1] = (ts[128] - ts[0]) / 256.0f;
    }
    if (tid < BB*HH){
        int b = (int)(tid/HH), h = (int)(tid%HH);
        float acc = l1b[h];
        #pragma unroll
        for (int d = 0; d < DD; d++) acc += x0[b*DD+d]*l1w[h*DD+d];
        g_y[tid] = acc;
    }
    for (long i = tid; i < WW*HH; i += stride) g_w0h[i] = __float2half_rn(w0[i]);
    for (long i = tid; i < WW*WW; i += stride) g_w1h[i] = __float2half_rn(w1[i]);
    for (long i = tid; i < WW*WW; i += stride) g_w2h[i] = __float2half_rn(w2[i]);
    // W3 fragment layout (half2 unit index bits):
    //   lc*65536 + h*1024 + c*128 + lane*4 + j    <- lanes fastest (coalesced)
    // j0: (n=lane>>2,   k=c*16+(lane&3)*2)   j1: same n, k+8
    // j2: (n=8+lane>>2, k=c*16+(lane&3)*2)   j3: same n, k+8
    const long NU = 33L*65536;
    for (long u = tid; u < NU; u += stride){
        int j = (int)(u & 3);
        int lane = (int)((u >> 2) & 31);
        int c = (int)((u >> 7) & 7);
        int h = (int)((u >> 10) & 63);
        int lc = (int)(u >> 16);
        int n = (lane >> 2) + ((j >> 1) ? 8 : 0);
        int l = lc*16 + n;
        int k = c*16 + (lane & 3)*2 + ((j & 1) ? 8 : 0);
        const float* src = w3 + ((size_t)h*LL + l)*WW + k;
        reinterpret_cast<__half2*>(g_w3f)[u] = __floats2half2_rn(src[0], src[1]);
    }
}

// ---------------- one fp16 MLP layer (phase A, N=8 per warp) ---------------
__device__ __forceinline__ void mlpA(const __half* cur, const __half* wsm,
        int wstr32, int nch, const float* __restrict__ bias,
        __half* nxt, __half* h3out, int rbase, int g, int tg, int nb, int nrows){
    const unsigned* cu = (const unsigned*)cur;
    const unsigned* wu = (const unsigned*)wsm;
    float acc[4] = {0.f,0.f,0.f,0.f};
    for (int ch = 0; ch < nch; ch++){
        unsigned a0 = cu[ g   *68 + ch*8 + tg  ];
        unsigned a1 = cu[(g+8)*68 + ch*8 + tg  ];
        unsigned a2 = cu[ g   *68 + ch*8 + tg+4];
        unsigned a3 = cu[(g+8)*68 + ch*8 + tg+4];
        unsigned b0 = wu[(nb+g)*wstr32 + ch*8 + tg  ];
        unsigned b1 = wu[(nb+g)*wstr32 + ch*8 + tg+4];
        mma_f16(acc, a0,a1,a2,a3, b0,b1);
    }
    int colb = nb + 2*tg;
    float z0 = acc[0]+bias[colb], z1 = acc[1]+bias[colb+1];
    __half2 v0 = __floats2half2_rn(fast_silu(z0), fast_silu(z1));
    if (h3out){
        if (g < nrows)
            *reinterpret_cast<__half2*>(&h3out[(rbase+g)*WW + colb]) = v0;
    } else {
        float z2 = acc[2]+bias[colb], z3 = acc[3]+bias[colb+1];
        __half2 v1 = __floats2half2_rn(fast_silu(z2), fast_silu(z3));
        *reinterpret_cast<__half2*>(&nxt[ g   *136 + colb]) = v0;
        *reinterpret_cast<__half2*>(&nxt[(g+8)*136 + colb]) = v1;
    }
}

// ================= persistent main kernel (512 threads, 132 CTAs) ==========
__global__ void __launch_bounds__(THREADS, 1) k_main(
        const float* __restrict__ logsig, const float* __restrict__ intervals,
        const float* __restrict__ b0, const float* __restrict__ b1,
        const float* __restrict__ b2, const float* __restrict__ b3){
    extern __shared__ char smc[];
    __half*  w0s   = (__half*) (smc + OFF_W0);
    __half*  w1s   = (__half*) (smc + OFF_W1);
    __half*  w2s   = (__half*) (smc + OFF_W2);
    float*   abias = (float*)  (smc + OFF_AB);
    __half*  act0  = (__half*) (smc + OFF_A0);
    __half*  act1  = (__half*) (smc + OFF_A1);
    __half*  sA    = (__half*) (smc + OFF_SA);
    __half2* sSig2 = (__half2*)(smc + OFF_SG);
    __half2* sBb3h = (__half2*)(smc + OFF_B3);
    float*   sK    = (float*)  (smc + OFF_SK);

    const int tid = threadIdx.x;
    const int cta = blockIdx.x;
    const int grp = cta / GROUPC;
    const int member = cta - grp*GROUPC;      // 0..32 (= l-chunk)
    const int wid = tid >> 5, lane = tid & 31;
    const int g = lane >> 2, tg = lane & 3;
    const float t0 = g_scal[0], dt = g_scal[1];
    unsigned bt = 0;

    const unsigned sAa = sm32(smc + OFF_SA);

    // ---- preamble: phase-A weights resident in smem for the whole run ----
    {
        unsigned w0a = sm32(w0s), w1a = sm32(w1s), w2a = sm32(w2s);
        #pragma unroll
        for (int j = 0; j < 2; j++){
            int id = tid + j*THREADS; int r = id >> 3, q = id & 7;
            CPA16(w0a + (unsigned)(r*144 + q*16), (const void*)((const char*)g_w0h + r*128 + q*16));
        }
        #pragma unroll
        for (int j = 0; j < 4; j++){
            int id = tid + j*THREADS; int r = id >> 4, q = id & 15;
            CPA16(w1a + (unsigned)(r*272 + q*16), (const void*)((const char*)g_w1h + r*256 + q*16));
        }
        #pragma unroll
        for (int j = 0; j < 4; j++){
            int id = tid + j*THREADS; int r = id >> 4, q = id & 15;
            CPA16(w2a + (unsigned)(r*272 + q*16), (const void*)((const char*)g_w2h + r*256 + q*16));
        }
        CPCOMMIT();
        if (tid < 384)
            abias[tid] = (tid < 128) ? b0[tid] : (tid < 256) ? b1[tid-128] : b2[tid-256];
        CPWAIT(0);
    }
    __syncthreads();

    // phase-B per-warp constants (16 warps = 8 M-tiles x 2 h-slots)
    const int mt = wid & 7, nh = wid >> 3;
    const int mrow = mt * 16;
    const int arow = mrow + (lane & 7) + (lane & 8);
    const int kofA = ((lane >> 4) & 1) * 8;
    const int rbase = grp * 128;
    const int l0 = member * 16;
    // fragment base: member block (256KB) + this lane's 16B slot
    const char* wfbase = (const char*)g_w3f + ((size_t)member << 18) + lane*16;

    for (int step = 0; step < NSTEPS; step++){
        for (int s = 0; s < 6; s++){
            // ------- Phase A: members 0..31, 4 rows each (btile-local) -----
            if (member < 32){
                int rbaseA = rbase + member*4;
                if (tid < 256){
                    int r = tid >> 6, h = tid & 63;
                    int gi = (rbaseA + r)*HH + h;
                    int prev = (s + 5) % 6;
                    float kp = 0.f;
                    if (step > 0 || s > 0){
                        size_t base = (size_t)grp*GROUPC*8192
                                    + (size_t)((member*4 + r)*64 + h);
                        #pragma unroll
                        for (int j = 0; j < GROUPC; j++)
                            kp += g_part[base + (size_t)j*8192];
                        g_k[prev][gi] = kp;
                    }
                    float y = g_y[gi];
                    if (s == 0){
                        if (step > 0){
                            float a = cBv[5]*kp;
                            #pragma unroll
                            for (int j = 0; j < 5; j++) a += cBv[j]*g_k[j][gi];
                            y += dt*a;
                            g_y[gi] = y;
                        }
                    } else {
                        float a = cA[s][s-1]*kp;
                        for (int j = 0; j < s-1; j++) a += cA[s][j]*g_k[j][gi];
                        y += dt*a;
                    }
                    act0[r*136 + h] = __float2half_rn(y);
                }
                if (tid < 384){   // zero pad rows 4..15, cols 0..63
                    int rr = 4 + (tid >> 5);
                    ((unsigned*)act0)[rr*68 + (tid & 31)] = 0u;
                }
                __syncthreads();
                int nb = wid * 8;
                mlpA(act0, w0s, 36, 4, abias,       act1, nullptr, rbaseA, g, tg, nb, 4);
                __syncthreads();
                mlpA(act1, w1s, 68, 8, abias + 128, act0, nullptr, rbaseA, g, tg, nb, 4);
                __syncthreads();
                mlpA(act0, w2s, 68, 8, abias + 256, nullptr, g_h3h, rbaseA, g, tg, nb, 4);
            }
            bt += GROUPC; group_barrier(grp, bt);

            // ------- Phase B: fp16 GEMM, coalesced B fragments (LDG.128) ---
            {
                float t = t0 + (float)step*dt + cCv[s]*dt;
                int idx = 0;
                #pragma unroll
                for (int j = 0; j < NIV; j++) idx += (intervals[j] < t) ? 1 : 0;

                // stage h3 tile (fp16, 32 KB)
                #pragma unroll
                for (int j = 0; j < 4; j++){
                    int id = tid + j*THREADS; int r = id >> 4, q = id & 15;
                    float4 v = *reinterpret_cast<const float4*>(
                        (const char*)g_h3h + (size_t)(rbase + r)*256 + q*16);
                    *reinterpret_cast<float4*>((char*)sA + r*272 + q*16) = v;
                }
                // sig pairs -> half2 [lpair][row]
                #pragma unroll
                for (int j = 0; j < 2; j++){
                    int e = tid + j*THREADS;
                    int r = e >> 3, p = e & 7;
                    const float* src = logsig + (size_t)(rbase + r)*LSTR
                                     + (size_t)idx*529 + 1 + l0 + 2*p;
                    sSig2[p*136 + r] = __floats2half2_rn(src[0], src[1]);
                }
                // bias pairs -> half2 [h][lpair]
                {
                    int h = tid >> 3, p = tid & 7;
                    sBb3h[h*8 + p] = __floats2half2_rn(b3[h*LL + l0 + 2*p],
                                                       b3[h*LL + l0 + 2*p + 1]);
                }
                __syncthreads();

                // A fragments register-resident for the whole stage
                unsigned aF[8][4];
                #pragma unroll
                for (int ch = 0; ch < 8; ch++)
                    ldsm_x4(aF[ch][0], aF[ch][1], aF[ch][2], aF[ch][3],
                            sAa + (unsigned)(arow*272 + (ch*16 + kofA)*2));

                // prefetch B fragments for first h (8 coalesced LDG.128)
                uint4 Bv[8];
                {
                    const char* wf = wfbase + ((size_t)nh << 12);
                    #pragma unroll
                    for (int c = 0; c < 8; c++)
                        Bv[c] = *reinterpret_cast<const uint4*>(wf + c*512);
                }

                const int rg = mrow + g, rg8 = rg + 8;
                for (int t2 = 0; t2 < 32; t2++){
                    int h = 2*t2 + nh;
                    float accL[4] = {0.f,0.f,0.f,0.f};
                    float accH[4] = {0.f,0.f,0.f,0.f};
                    #pragma unroll
                    for (int c = 0; c < 8; c++){
                        mma_f16(accL, aF[c][0],aF[c][1],aF[c][2],aF[c][3], Bv[c].x, Bv[c].y);
                        mma_f16(accH, aF[c][0],aF[c][1],aF[c][2],aF[c][3], Bv[c].z, Bv[c].w);
                    }
                    // issue next h's B loads (latency covered by epilogue)
                    if (t2 < 31){
                        const char* wf = wfbase + ((size_t)(h+2) << 12);
                        #pragma unroll
                        for (int c = 0; c < 8; c++)
                            Bv[c] = *reinterpret_cast<const uint4*>(wf + c*512);
                    }
                    // epilogue: bias + tanh(f16x2) + sig, reduce 16 l's
                    __half2 biasL = sBb3h[h*8 + tg];
                    __half2 biasH = sBb3h[h*8 + 4 + tg];
                    __half2 sigLa = sSig2[tg*136 + rg],     sigLb = sSig2[tg*136 + rg8];
                    __half2 sigHa = sSig2[(4+tg)*136 + rg], sigHb = sSig2[(4+tg)*136 + rg8];
                    __half2 zL0 = __hadd2(__floats2half2_rn(accL[0],accL[1]), biasL);
                    __half2 zH0 = __hadd2(__floats2half2_rn(accH[0],accH[1]), biasH);
                    __half2 zL1 = __hadd2(__floats2half2_rn(accL[2],accL[3]), biasL);
                    __half2 zH1 = __hadd2(__floats2half2_rn(accH[2],accH[3]), biasH);
                    __half2 p0 = __hmul2(tanh2(zL0), sigLa);
                    p0 = __hfma2(tanh2(zH0), sigHa, p0);
                    __half2 p1 = __hmul2(tanh2(zL1), sigLb);
                    p1 = __hfma2(tanh2(zH1), sigHb, p1);
                    float2 f0 = __half22float2(p0); float s0 = f0.x + f0.y;
                    float2 f1 = __half22float2(p1); float s1 = f1.x + f1.y;
                    s0 += __shfl_xor_sync(0xffffffffu, s0, 1);
                    s0 += __shfl_xor_sync(0xffffffffu, s0, 2);
                    s1 += __shfl_xor_sync(0xffffffffu, s1, 1);
                    s1 += __shfl_xor_sync(0xffffffffu, s1, 2);
                    if (tg == 0){
                        sK[rg *65 + h] = s0;
                        sK[rg8*65 + h] = s1;
                    }
                }
                __syncthreads();
                // flush k partials: sK -> g_part[cta]
                #pragma unroll
                for (int j = 0; j < 16; j++){
                    int e = tid + j*THREADS;
                    int rr = e >> 6, hh = e & 63;
                    g_part[(size_t)cta*8192 + e] = sK[rr*65 + hh];
                }
            }
            bt += GROUPC; group_barrier(grp, bt);
        }
    }
}

// ================= final: reduce k5, y update + logits + softmax ===========
__global__ void k_final(const float* __restrict__ l2w, const float* __restrict__ l2b,
                        float* __restrict__ out){
    int b = blockIdx.x*blockDim.x + threadIdx.x;
    if (b >= BB) return;
    float dt = g_scal[1];
    int btile = b >> 7, rl = b & 127;
    size_t pbase = (size_t)(btile*GROUPC)*8192 + (size_t)rl*64;
    float yv[HH];
    for (int h = 0; h < HH; h++){
        int gi = b*HH + h;
        float k5 = 0.f;
        #pragma unroll
        for (int lc = 0; lc < GROUPC; lc++) k5 += g_part[pbase + (size_t)lc*8192 + h];
        float a = cBv[5]*k5;
        #pragma unroll
        for (int j = 0; j < 5; j++) a += cBv[j]*g_k[j][gi];
        yv[h] = g_y[gi] + dt*a;
    }
    float lg[10]; float mx = -1e30f;
    #pragma unroll
    for (int o = 0; o < 10; o++){
        float a = l2b[o];
        for (int h = 0; h < HH; h++) a += yv[h]*l2w[o*HH + h];
        lg[o] = a; mx = fmaxf(mx, a);
    }
    float ssum = 0.f;
    #pragma unroll
    for (int o = 0; o < 10; o++){ lg[o] = expf(lg[o] - mx); ssum += lg[o]; }
    float inv = 1.0f / ssum;
    #pragma unroll
    for (int o = 0; o < 10; o++) out[b*10 + o] = lg[o]*inv;
}

// ================= launcher: 5 graph nodes =================================
extern "C" void kernel_launch(void* const* d_in, const int* in_sizes, int n_in,
                              void* d_out, int out_size){
    const float* ts        = (const float*)d_in[0];
    const float* logsig    = (const float*)d_in[1];
    const float* x0        = (const float*)d_in[2];
    const float* intervals = (const float*)d_in[3];
    const float* w0 = (const float*)d_in[4];   const float* b0 = (const float*)d_in[5];
    const float* w1 = (const float*)d_in[6];   const float* b1 = (const float*)d_in[7];
    const float* w2 = (const float*)d_in[8];   const float* b2 = (const float*)d_in[9];
    const float* w3 = (const float*)d_in[10];  const float* b3 = (const float*)d_in[11];
    const float* l1w = (const float*)d_in[12]; const float* l1b = (const float*)d_in[13];
    const float* l2w = (const float*)d_in[14]; const float* l2b = (const float*)d_in[15];
    float* out = (float*)d_out;

    cudaFuncSetAttribute(k_main, cudaFuncAttributeMaxDynamicSharedMemorySize, SMEM_TOT);

    // two no-op launches keep the fixed ncu -s window on k_main
    k_nop<<<1, 32>>>();
    k_nop<<<1, 32>>>();
    k_init<<<4224, 256>>>(ts, x0, l1w, l1b, w0, w1, w2, w3);
    k_main<<<GRIDN, THREADS, SMEM_TOT>>>(logsig, intervals, b0, b1, b2, b3);
    k_final<<<2, 256>>>(l2w, l2b, out);
}